// round 1
// baseline (speedup 1.0000x reference)
#include <cuda_runtime.h>
#include <math.h>

// Problem constants
#define BB 4
#define TT 2048
#define DD 128
#define HH 8
#define DK 16
#define QT 16          // q rows per attention block
#define SSTR 20        // padded stride (floats) of ss[k][q] rows

// Scratch (static device globals; no allocation allowed)
__device__ float g_Q[BB*TT*DD];
__device__ float g_K[BB*TT*DD];
__device__ float g_V[BB*TT*DD];
__device__ float g_ctx[BB*TT*DD];

// ---------------------------------------------------------------------------
// Kernel 1: row-tiled projection  out = X @ W + b   (X:[8192,128], W:[128,128])
// 16 rows per block, 128 threads (thread = output column)
// ---------------------------------------------------------------------------
__global__ void proj_kernel(const float* __restrict__ X,
                            const float* __restrict__ W,
                            const float* __restrict__ bias,
                            float* __restrict__ out)
{
    __shared__ float xs[16][128];
    const int tid  = threadIdx.x;
    const int row0 = blockIdx.x * 16;

    #pragma unroll
    for (int r = 0; r < 16; r++)
        xs[r][tid] = X[(size_t)(row0 + r) * DD + tid];
    __syncthreads();

    float acc[16];
    const float bv = bias[tid];
    #pragma unroll
    for (int r = 0; r < 16; r++) acc[r] = bv;

    for (int k = 0; k < DD; k++) {
        const float wv = W[k * DD + tid];
        #pragma unroll
        for (int r = 0; r < 16; r++)
            acc[r] = fmaf(xs[r][k], wv, acc[r]);
    }

    #pragma unroll
    for (int r = 0; r < 16; r++)
        out[(size_t)(row0 + r) * DD + tid] = acc[r];
}

// ---------------------------------------------------------------------------
// Kernel 2: attention for one (b,h,q-tile of 16 rows)
//   - scores into shared ss[k][q] (stride SSTR)
//   - exp in place + row sums (no max-subtraction: scores are O(1))
//   - write attn = e * (1/l)  (float4 stores)
//   - ctx = (e @ V) * (1/l)   (register-tiled 4x4, k split 16 ways)
// Shared: ss 2048*20 | qs 16*16 | vs 128*16 | red 256*16 | rowsum 16
// ---------------------------------------------------------------------------
__global__ void attn_kernel(const float* __restrict__ Qg,
                            const float* __restrict__ Kg,
                            const float* __restrict__ Vg,
                            float* __restrict__ attn,
                            float* __restrict__ ctx)
{
    extern __shared__ float smem[];
    float* ss     = smem;                       // TT*SSTR
    float* qsm    = ss   + TT * SSTR;           // QT*DK
    float* vsm    = qsm  + QT * DK;             // 128*DK
    float* red    = vsm  + 128 * DK;            // 256*16
    float* rowsum = red  + 256 * 16;            // QT

    const int tid = threadIdx.x;                // 256 threads
    const int q0  = blockIdx.x * QT;
    const int bh  = blockIdx.y;                 // b*H + h
    const int bb  = bh >> 3;
    const int h   = bh & 7;
    const float scale = 0.25f;                  // 1/sqrt(16)

    // Load Q tile (16x16): one element per thread
    {
        const int q = tid >> 4, d = tid & 15;
        qsm[q * DK + d] = Qg[((size_t)bb * TT + q0 + q) * DD + h * DK + d];
    }
    if (tid < QT) rowsum[tid] = 0.f;
    __syncthreads();

    // ---- scores: each thread handles 8 k rows ----
    const float4* qv = (const float4*)qsm;      // qv[q*4 + dg]
    for (int j = 0; j < 8; j++) {
        const int k = j * 256 + tid;
        const float4* Kp = (const float4*)(Kg + ((size_t)bb * TT + k) * DD + h * DK);
        const float4 k0 = Kp[0], k1 = Kp[1], k2 = Kp[2], k3 = Kp[3];
        #pragma unroll
        for (int q = 0; q < QT; q++) {
            const float4 a0 = qv[q*4+0], a1 = qv[q*4+1], a2 = qv[q*4+2], a3 = qv[q*4+3];
            float acc;
            acc  = a0.x*k0.x; acc = fmaf(a0.y, k0.y, acc);
            acc  = fmaf(a0.z, k0.z, acc); acc = fmaf(a0.w, k0.w, acc);
            acc  = fmaf(a1.x, k1.x, acc); acc = fmaf(a1.y, k1.y, acc);
            acc  = fmaf(a1.z, k1.z, acc); acc = fmaf(a1.w, k1.w, acc);
            acc  = fmaf(a2.x, k2.x, acc); acc = fmaf(a2.y, k2.y, acc);
            acc  = fmaf(a2.z, k2.z, acc); acc = fmaf(a2.w, k2.w, acc);
            acc  = fmaf(a3.x, k3.x, acc); acc = fmaf(a3.y, k3.y, acc);
            acc  = fmaf(a3.w, k3.w, acc); acc = fmaf(a3.z, k3.z, acc);
            ss[k * SSTR + q] = acc * scale;
        }
    }
    __syncthreads();

    // ---- exp in place + per-row partial sums ----
    float psum[QT];
    #pragma unroll
    for (int q = 0; q < QT; q++) psum[q] = 0.f;
    for (int j = 0; j < 8; j++) {
        const int k = j * 256 + tid;
        #pragma unroll
        for (int q = 0; q < QT; q++) {
            const float e = __expf(ss[k * SSTR + q]);
            ss[k * SSTR + q] = e;
            psum[q] += e;
        }
    }
    #pragma unroll
    for (int q = 0; q < QT; q++) {
        float v = psum[q];
        v += __shfl_down_sync(0xffffffffu, v, 16);
        v += __shfl_down_sync(0xffffffffu, v, 8);
        v += __shfl_down_sync(0xffffffffu, v, 4);
        v += __shfl_down_sync(0xffffffffu, v, 2);
        v += __shfl_down_sync(0xffffffffu, v, 1);
        if ((tid & 31) == 0) atomicAdd(&rowsum[q], v);
    }
    __syncthreads();
    if (tid < QT) rowsum[tid] = 1.f / rowsum[tid];   // now holds 1/l
    __syncthreads();

    // ---- write normalized attn (float4 stores) ----
    {
        const size_t attn_base = ((size_t)bh * TT + q0) * TT;
        for (int i = tid; i < QT * TT / 4; i += 256) {
            const int q  = i >> 9;            // 512 float4 per row
            const int kk = (i & 511) << 2;
            const float rs = rowsum[q];
            float4 v;
            v.x = ss[(kk + 0) * SSTR + q] * rs;
            v.y = ss[(kk + 1) * SSTR + q] * rs;
            v.z = ss[(kk + 2) * SSTR + q] * rs;
            v.w = ss[(kk + 3) * SSTR + q] * rs;
            *(float4*)(attn + attn_base + (size_t)q * TT + kk) = v;
        }
    }

    // ---- ctx = e @ V, register tiled 4(q) x 4(d), k split 16 ways ----
    const int kp = tid >> 4;
    const int qg = (tid >> 2) & 3;
    const int dg = tid & 3;
    float acc[4][4];
    #pragma unroll
    for (int a = 0; a < 4; a++)
        #pragma unroll
        for (int c = 0; c < 4; c++) acc[a][c] = 0.f;

    for (int kt = 0; kt < 16; kt++) {
        __syncthreads();   // protect vsm reuse
        #pragma unroll
        for (int j = 0; j < 2; j++) {
            const int i   = tid * 2 + j;      // 0..511 float4
            const int row = i >> 2, dgi = i & 3;
            ((float4*)vsm)[row * 4 + dgi] =
                ((const float4*)(Vg + ((size_t)bb * TT + kt * 128 + row) * DD + h * DK))[dgi];
        }
        __syncthreads();
        #pragma unroll
        for (int i = 0; i < 8; i++) {
            const int kl = kp * 8 + i;
            const int k  = kt * 128 + kl;
            const float4 s = *(const float4*)&ss[k * SSTR + qg * 4];
            const float4 v = ((const float4*)vsm)[kl * 4 + dg];
            acc[0][0] = fmaf(s.x, v.x, acc[0][0]); acc[0][1] = fmaf(s.x, v.y, acc[0][1]);
            acc[0][2] = fmaf(s.x, v.z, acc[0][2]); acc[0][3] = fmaf(s.x, v.w, acc[0][3]);
            acc[1][0] = fmaf(s.y, v.x, acc[1][0]); acc[1][1] = fmaf(s.y, v.y, acc[1][1]);
            acc[1][2] = fmaf(s.y, v.z, acc[1][2]); acc[1][3] = fmaf(s.y, v.w, acc[1][3]);
            acc[2][0] = fmaf(s.z, v.x, acc[2][0]); acc[2][1] = fmaf(s.z, v.y, acc[2][1]);
            acc[2][2] = fmaf(s.z, v.z, acc[2][2]); acc[2][3] = fmaf(s.z, v.w, acc[2][3]);
            acc[3][0] = fmaf(s.w, v.x, acc[3][0]); acc[3][1] = fmaf(s.w, v.y, acc[3][1]);
            acc[3][2] = fmaf(s.w, v.z, acc[3][2]); acc[3][3] = fmaf(s.w, v.w, acc[3][3]);
        }
    }

    __syncthreads();
    #pragma unroll
    for (int qi = 0; qi < 4; qi++)
        #pragma unroll
        for (int di = 0; di < 4; di++)
            red[tid * 16 + qi * 4 + di] = acc[qi][di];
    __syncthreads();

    {
        const int q = tid >> 4, d = tid & 15;
        const int qg2 = q >> 2, qi = q & 3, dg2 = d >> 2, di = d & 3;
        float s = 0.f;
        #pragma unroll
        for (int kp2 = 0; kp2 < 16; kp2++)
            s += red[(kp2 * 16 + qg2 * 4 + dg2) * 16 + qi * 4 + di];
        s *= rowsum[q];
        ctx[((size_t)bb * TT + q0 + q) * DD + h * DK + d] = s;
    }
}

// ---------------------------------------------------------------------------
// Kernel 3: out = LN(ctx @ Wo + bo + queries) * gamma + beta
// ---------------------------------------------------------------------------
__global__ void out_kernel(const float* __restrict__ ctxg,
                           const float* __restrict__ Wo,
                           const float* __restrict__ bo,
                           const float* __restrict__ resid,
                           const float* __restrict__ gamma,
                           const float* __restrict__ beta,
                           float* __restrict__ out)
{
    __shared__ float xs[16][128];
    __shared__ float mrow[16], rrow[16];
    const int tid  = threadIdx.x;   // 128
    const int row0 = blockIdx.x * 16;

    #pragma unroll
    for (int r = 0; r < 16; r++)
        xs[r][tid] = ctxg[(size_t)(row0 + r) * DD + tid];
    __syncthreads();

    float acc[16];
    const float bv = bo[tid];
    #pragma unroll
    for (int r = 0; r < 16; r++) acc[r] = bv;
    for (int k = 0; k < DD; k++) {
        const float wv = Wo[k * DD + tid];
        #pragma unroll
        for (int r = 0; r < 16; r++)
            acc[r] = fmaf(xs[r][k], wv, acc[r]);
    }
    __syncthreads();   // done reading xs; will overwrite

    #pragma unroll
    for (int r = 0; r < 16; r++) {
        acc[r] += resid[(size_t)(row0 + r) * DD + tid];
        xs[r][tid] = acc[r];
    }
    __syncthreads();

    // mean/var: 8 threads per row
    {
        const int r = tid >> 3, l8 = tid & 7;
        float s = 0.f, s2 = 0.f;
        for (int c = l8; c < 128; c += 8) {
            const float v = xs[r][c];
            s += v; s2 = fmaf(v, v, s2);
        }
        #pragma unroll
        for (int off = 4; off > 0; off >>= 1) {
            s  += __shfl_down_sync(0xffffffffu, s,  off, 8);
            s2 += __shfl_down_sync(0xffffffffu, s2, off, 8);
        }
        if (l8 == 0) {
            const float m   = s * (1.f / 128.f);
            const float var = s2 * (1.f / 128.f) - m * m;
            mrow[r] = m;
            rrow[r] = rsqrtf(var + 1e-5f);
        }
    }
    __syncthreads();

    const float g = gamma[tid], bt = beta[tid];
    #pragma unroll
    for (int r = 0; r < 16; r++)
        out[(size_t)(row0 + r) * DD + tid] = (acc[r] - mrow[r]) * rrow[r] * g + bt;
}

// ---------------------------------------------------------------------------
extern "C" void kernel_launch(void* const* d_in, const int* in_sizes, int n_in,
                              void* d_out, int out_size)
{
    const float* queries = (const float*)d_in[0];
    const float* keys    = (const float*)d_in[1];
    const float* values  = (const float*)d_in[2];
    const float* Wq      = (const float*)d_in[3];
    const float* bq      = (const float*)d_in[4];
    const float* Wk      = (const float*)d_in[5];
    const float* bk      = (const float*)d_in[6];
    const float* Wv      = (const float*)d_in[7];
    const float* bv      = (const float*)d_in[8];
    const float* Wo      = (const float*)d_in[9];
    const float* bo      = (const float*)d_in[10];
    const float* gamma   = (const float*)d_in[11];
    const float* beta    = (const float*)d_in[12];

    float* out  = (float*)d_out;                       // [4,2048,128]
    float* attn = out + (size_t)BB * TT * DD;          // [4,8,2048,2048]

    float *Qd, *Kd, *Vd, *Cd;
    cudaGetSymbolAddress((void**)&Qd, g_Q);
    cudaGetSymbolAddress((void**)&Kd, g_K);
    cudaGetSymbolAddress((void**)&Vd, g_V);
    cudaGetSymbolAddress((void**)&Cd, g_ctx);

    const int rows = BB * TT;                          // 8192
    proj_kernel<<<rows / 16, 128>>>(queries, Wq, bq, Qd);
    proj_kernel<<<rows / 16, 128>>>(keys,    Wk, bk, Kd);
    proj_kernel<<<rows / 16, 128>>>(values,  Wv, bv, Vd);

    const int smem_bytes = (TT * SSTR + QT * DK + 128 * DK + 256 * 16 + QT) * 4;
    cudaFuncSetAttribute(attn_kernel, cudaFuncAttributeMaxDynamicSharedMemorySize, smem_bytes);
    attn_kernel<<<dim3(TT / QT, BB * HH), 256, smem_bytes>>>(Qd, Kd, Vd, attn, Cd);

    out_kernel<<<rows / 16, 128>>>(Cd, Wo, bo, queries, gamma, beta, out);
}

// round 4
// speedup vs baseline: 2.5905x; 2.5905x over previous
#include <cuda_runtime.h>
#include <cuda_bf16.h>
#include <stdint.h>
#include <math.h>

#define BB 4
#define TT 2048
#define DD 128
#define HH 8
#define DK 16
#define KSTR 20          // K tile smem stride (floats) - conflict-free for b-frag LDS
#define VSTR 136         // V^T tile stride (bf16)

__device__ float g_Q[BB*TT*DD];
__device__ float g_K[BB*TT*DD];
__device__ float g_V[BB*TT*DD];
__device__ float g_ctx[BB*TT*DD];

// ---------------------------------------------------------------------------
__device__ __forceinline__ uint32_t f2tf32(float x) {
    uint32_t r;
    asm("cvt.rna.tf32.f32 %0, %1;" : "=r"(r) : "f"(x));
    return r;
}

__device__ __forceinline__ void mma_tf32(float c[4], const uint32_t a[4],
                                         uint32_t b0, uint32_t b1) {
    asm volatile(
        "mma.sync.aligned.m16n8k8.row.col.f32.tf32.tf32.f32 "
        "{%0,%1,%2,%3}, {%4,%5,%6,%7}, {%8,%9}, {%0,%1,%2,%3};"
        : "+f"(c[0]), "+f"(c[1]), "+f"(c[2]), "+f"(c[3])
        : "r"(a[0]), "r"(a[1]), "r"(a[2]), "r"(a[3]), "r"(b0), "r"(b1));
}

__device__ __forceinline__ void mma_bf16(float c[4], const uint32_t a[4],
                                         uint32_t b0, uint32_t b1) {
    asm volatile(
        "mma.sync.aligned.m16n8k16.row.col.f32.bf16.bf16.f32 "
        "{%0,%1,%2,%3}, {%4,%5,%6,%7}, {%8,%9}, {%0,%1,%2,%3};"
        : "+f"(c[0]), "+f"(c[1]), "+f"(c[2]), "+f"(c[3])
        : "r"(a[0]), "r"(a[1]), "r"(a[2]), "r"(a[3]), "r"(b0), "r"(b1));
}

__device__ __forceinline__ uint32_t pack_bf16x2(float lo, float hi) {
    __nv_bfloat162 v = __floats2bfloat162_rn(lo, hi);   // .x = lo half
    return *reinterpret_cast<uint32_t*>(&v);
}

// ---------------------------------------------------------------------------
// Attention kernel: grid (TT/128, BB*HH), 128 threads (4 warps, m32 per warp)
// ---------------------------------------------------------------------------
__global__ void __launch_bounds__(128, 4)
attn_mma_kernel(const float* __restrict__ Qg,
                const float* __restrict__ Kg,
                const float* __restrict__ Vg,
                float* __restrict__ attn,
                float* __restrict__ ctx)
{
    __shared__ uint32_t sKhi[128 * KSTR];
    __shared__ uint32_t sKlo[128 * KSTR];
    __shared__ uint32_t sVt[DK * (VSTR / 2)];      // bf16 V^T tile, u32 view
    __shared__ float    sRinv[128];

    const int tid  = threadIdx.x;
    const int lane = tid & 31;
    const int wq   = tid >> 5;
    const int g    = lane >> 2;      // groupID
    const int tig  = lane & 3;       // thread in group

    const int q0 = blockIdx.x * 128;
    const int bh = blockIdx.y;
    const int bb = bh >> 3;
    const int h  = bh & 7;

    // ---- Q fragments (scaled by 0.25 = 1/sqrt(dk), exact power of 2) ----
    uint32_t qhi[2][2][4], qlo[2][2][4];
    #pragma unroll
    for (int m = 0; m < 2; m++) {
        const int rm = q0 + wq * 32 + m * 16 + g;
        #pragma unroll
        for (int s = 0; s < 2; s++) {
            const int c = h * DK + s * 8 + tig;
            float x[4];
            x[0] = 0.25f * Qg[((size_t)bb * TT + rm    ) * DD + c];
            x[1] = 0.25f * Qg[((size_t)bb * TT + rm + 8) * DD + c];
            x[2] = 0.25f * Qg[((size_t)bb * TT + rm    ) * DD + c + 4];
            x[3] = 0.25f * Qg[((size_t)bb * TT + rm + 8) * DD + c + 4];
            #pragma unroll
            for (int i = 0; i < 4; i++) {
                qhi[m][s][i] = f2tf32(x[i]);
                qlo[m][s][i] = f2tf32(x[i] - __uint_as_float(qhi[m][s][i]));
            }
        }
    }

    // =============================== SWEEP 1 ===============================
    float ps[2][2] = {{0.f, 0.f}, {0.f, 0.f}};

    for (int kt = 0; kt < TT / 128; kt++) {
        __syncthreads();
        {   // load K tile (hi only)
            const int r = tid;
            const float4* Ks = (const float4*)(Kg + ((size_t)bb * TT + kt * 128 + r) * DD + h * DK);
            #pragma unroll
            for (int c4 = 0; c4 < 4; c4++) {
                float4 v = Ks[c4];
                uint4 hi;
                hi.x = f2tf32(v.x); hi.y = f2tf32(v.y);
                hi.z = f2tf32(v.z); hi.w = f2tf32(v.w);
                *(uint4*)&sKhi[r * KSTR + c4 * 4] = hi;
            }
        }
        __syncthreads();

        #pragma unroll 4
        for (int ns = 0; ns < 16; ns++) {
            uint32_t b0[2], b1[2];
            #pragma unroll
            for (int s = 0; s < 2; s++) {
                const int base = (ns * 8 + g) * KSTR + s * 8 + tig;
                b0[s] = sKhi[base];
                b1[s] = sKhi[base + 4];
            }
            #pragma unroll
            for (int m = 0; m < 2; m++) {
                float C[4] = {0.f, 0.f, 0.f, 0.f};
                mma_tf32(C, qhi[m][0], b0[0], b1[0]);
                mma_tf32(C, qhi[m][1], b0[1], b1[1]);
                ps[m][0] += __expf(C[0]) + __expf(C[1]);
                ps[m][1] += __expf(C[2]) + __expf(C[3]);
            }
        }
    }

    // quad reduce + publish 1/rowsum
    #pragma unroll
    for (int m = 0; m < 2; m++) {
        #pragma unroll
        for (int i = 0; i < 2; i++) {
            float v = ps[m][i];
            v += __shfl_xor_sync(0xffffffffu, v, 1);
            v += __shfl_xor_sync(0xffffffffu, v, 2);
            ps[m][i] = v;
        }
        if (tig == 0) {
            sRinv[wq * 32 + m * 16 + g]     = 1.0f / ps[m][0];
            sRinv[wq * 32 + m * 16 + g + 8] = 1.0f / ps[m][1];
        }
    }
    __syncthreads();
    float ri[2][2];
    #pragma unroll
    for (int m = 0; m < 2; m++) {
        ri[m][0] = sRinv[wq * 32 + m * 16 + g];
        ri[m][1] = sRinv[wq * 32 + m * 16 + g + 8];
    }

    // =============================== SWEEP 2 ===============================
    float cc[2][2][4];
    #pragma unroll
    for (int m = 0; m < 2; m++)
        #pragma unroll
        for (int n = 0; n < 2; n++)
            #pragma unroll
            for (int i = 0; i < 4; i++) cc[m][n][i] = 0.f;

    const size_t abase_w = ((size_t)bh * TT + q0 + wq * 32) * TT;

    for (int kt = 0; kt < TT / 128; kt++) {
        __syncthreads();
        {   // load K (hi+lo) and V^T (bf16)
            const int r = tid;
            const float4* Ks = (const float4*)(Kg + ((size_t)bb * TT + kt * 128 + r) * DD + h * DK);
            const float4* Vs = (const float4*)(Vg + ((size_t)bb * TT + kt * 128 + r) * DD + h * DK);
            __nv_bfloat16* vt = (__nv_bfloat16*)sVt;
            #pragma unroll
            for (int c4 = 0; c4 < 4; c4++) {
                float4 v = Ks[c4];
                uint4 hi, lo;
                hi.x = f2tf32(v.x); lo.x = f2tf32(v.x - __uint_as_float(hi.x));
                hi.y = f2tf32(v.y); lo.y = f2tf32(v.y - __uint_as_float(hi.y));
                hi.z = f2tf32(v.z); lo.z = f2tf32(v.z - __uint_as_float(hi.z));
                hi.w = f2tf32(v.w); lo.w = f2tf32(v.w - __uint_as_float(hi.w));
                *(uint4*)&sKhi[r * KSTR + c4 * 4] = hi;
                *(uint4*)&sKlo[r * KSTR + c4 * 4] = lo;

                float4 vv = Vs[c4];
                vt[(c4 * 4 + 0) * VSTR + r] = __float2bfloat16(vv.x);
                vt[(c4 * 4 + 1) * VSTR + r] = __float2bfloat16(vv.y);
                vt[(c4 * 4 + 2) * VSTR + r] = __float2bfloat16(vv.z);
                vt[(c4 * 4 + 3) * VSTR + r] = __float2bfloat16(vv.w);
            }
        }
        __syncthreads();

        #pragma unroll 2
        for (int j = 0; j < 8; j++) {          // ns pairs -> one k16 for ctx mma
            uint32_t apk[2][4];
            #pragma unroll
            for (int nsl = 0; nsl < 2; nsl++) {
                const int ns = 2 * j + nsl;
                uint32_t bh0[2], bh1[2], bl0[2], bl1[2];
                #pragma unroll
                for (int s = 0; s < 2; s++) {
                    const int base = (ns * 8 + g) * KSTR + s * 8 + tig;
                    bh0[s] = sKhi[base];  bh1[s] = sKhi[base + 4];
                    bl0[s] = sKlo[base];  bl1[s] = sKlo[base + 4];
                }
                #pragma unroll
                for (int m = 0; m < 2; m++) {
                    float C[4] = {0.f, 0.f, 0.f, 0.f};
                    #pragma unroll
                    for (int s = 0; s < 2; s++) {
                        mma_tf32(C, qhi[m][s], bh0[s], bh1[s]);
                        mma_tf32(C, qhi[m][s], bl0[s], bl1[s]);
                        mma_tf32(C, qlo[m][s], bh0[s], bh1[s]);
                    }
                    const float p0 = __expf(C[0]) * ri[m][0];
                    const float p1 = __expf(C[1]) * ri[m][0];
                    const float p2 = __expf(C[2]) * ri[m][1];
                    const float p3 = __expf(C[3]) * ri[m][1];

                    // attn store (normalized, fp32, 32B sectors per quad)
                    float* ap = attn + abase_w + (size_t)(m * 16 + g) * TT
                              + kt * 128 + ns * 8 + 2 * tig;
                    *(float2*)ap            = make_float2(p0, p1);
                    *(float2*)(ap + 8 * TT) = make_float2(p2, p3);

                    // pack for ctx A fragment (C layout == bf16 A layout)
                    apk[m][nsl ? 2 : 0] = pack_bf16x2(p0, p1);
                    apk[m][nsl ? 3 : 1] = pack_bf16x2(p2, p3);
                }
            }
            // ctx += P(16 cols) @ V
            #pragma unroll
            for (int n2 = 0; n2 < 2; n2++) {
                const int vi = (n2 * 8 + g) * (VSTR / 2) + 8 * j + tig;
                const uint32_t vb0 = sVt[vi];
                const uint32_t vb1 = sVt[vi + 4];
                mma_bf16(cc[0][n2], apk[0], vb0, vb1);
                mma_bf16(cc[1][n2], apk[1], vb0, vb1);
            }
        }
    }

    // ---- write ctx ----
    #pragma unroll
    for (int m = 0; m < 2; m++) {
        const int row = q0 + wq * 32 + m * 16 + g;
        #pragma unroll
        for (int n2 = 0; n2 < 2; n2++) {
            float* cp = ctx + ((size_t)bb * TT + row) * DD + h * DK + n2 * 8 + 2 * tig;
            *(float2*)cp            = make_float2(cc[m][n2][0], cc[m][n2][1]);
            *(float2*)(cp + 8 * DD) = make_float2(cc[m][n2][2], cc[m][n2][3]);
        }
    }
}

// ---------------------------------------------------------------------------
// Merged QKV projection: grid (rows/16, 3), 128 threads
// ---------------------------------------------------------------------------
__global__ void proj3_kernel(const float* __restrict__ q,
                             const float* __restrict__ k,
                             const float* __restrict__ v,
                             const float* __restrict__ Wq, const float* __restrict__ bq,
                             const float* __restrict__ Wk, const float* __restrict__ bk,
                             const float* __restrict__ Wv, const float* __restrict__ bv,
                             float* __restrict__ Qd, float* __restrict__ Kd,
                             float* __restrict__ Vd)
{
    const float* X; const float* W; const float* bias; float* out;
    if (blockIdx.y == 0)      { X = q; W = Wq; bias = bq; out = Qd; }
    else if (blockIdx.y == 1) { X = k; W = Wk; bias = bk; out = Kd; }
    else                      { X = v; W = Wv; bias = bv; out = Vd; }

    __shared__ float xs[16][128];
    const int tid  = threadIdx.x;
    const int row0 = blockIdx.x * 16;

    #pragma unroll
    for (int r = 0; r < 16; r++)
        xs[r][tid] = X[(size_t)(row0 + r) * DD + tid];
    __syncthreads();

    float acc[16];
    const float bvv = bias[tid];
    #pragma unroll
    for (int r = 0; r < 16; r++) acc[r] = bvv;

    for (int kk = 0; kk < DD; kk++) {
        const float wv = W[kk * DD + tid];
        #pragma unroll
        for (int r = 0; r < 16; r++)
            acc[r] = fmaf(xs[r][kk], wv, acc[r]);
    }

    #pragma unroll
    for (int r = 0; r < 16; r++)
        out[(size_t)(row0 + r) * DD + tid] = acc[r];
}

// ---------------------------------------------------------------------------
// Output projection + residual + LayerNorm
// ---------------------------------------------------------------------------
__global__ void out_kernel(const float* __restrict__ ctxg,
                           const float* __restrict__ Wo,
                           const float* __restrict__ bo,
                           const float* __restrict__ resid,
                           const float* __restrict__ gamma,
                           const float* __restrict__ beta,
                           float* __restrict__ out)
{
    __shared__ float xs[16][128];
    __shared__ float mrow[16], rrow[16];
    const int tid  = threadIdx.x;   // 128
    const int row0 = blockIdx.x * 16;

    #pragma unroll
    for (int r = 0; r < 16; r++)
        xs[r][tid] = ctxg[(size_t)(row0 + r) * DD + tid];
    __syncthreads();

    float acc[16];
    const float bv = bo[tid];
    #pragma unroll
    for (int r = 0; r < 16; r++) acc[r] = bv;
    for (int k = 0; k < DD; k++) {
        const float wv = Wo[k * DD + tid];
        #pragma unroll
        for (int r = 0; r < 16; r++)
            acc[r] = fmaf(xs[r][k], wv, acc[r]);
    }
    __syncthreads();

    #pragma unroll
    for (int r = 0; r < 16; r++) {
        acc[r] += resid[(size_t)(row0 + r) * DD + tid];
        xs[r][tid] = acc[r];
    }
    __syncthreads();

    {
        const int r = tid >> 3, l8 = tid & 7;
        float s = 0.f, s2 = 0.f;
        for (int c = l8; c < 128; c += 8) {
            const float v = xs[r][c];
            s += v; s2 = fmaf(v, v, s2);
        }
        #pragma unroll
        for (int off = 4; off > 0; off >>= 1) {
            s  += __shfl_down_sync(0xffffffffu, s,  off, 8);
            s2 += __shfl_down_sync(0xffffffffu, s2, off, 8);
        }
        if (l8 == 0) {
            const float m   = s * (1.f / 128.f);
            const float var = s2 * (1.f / 128.f) - m * m;
            mrow[r] = m;
            rrow[r] = rsqrtf(var + 1e-5f);
        }
    }
    __syncthreads();

    const float gm = gamma[tid], bt = beta[tid];
    #pragma unroll
    for (int r = 0; r < 16; r++)
        out[(size_t)(row0 + r) * DD + tid] = (acc[r] - mrow[r]) * rrow[r] * gm + bt;
}

// ---------------------------------------------------------------------------
extern "C" void kernel_launch(void* const* d_in, const int* in_sizes, int n_in,
                              void* d_out, int out_size)
{
    const float* queries = (const float*)d_in[0];
    const float* keys    = (const float*)d_in[1];
    const float* values  = (const float*)d_in[2];
    const float* Wq      = (const float*)d_in[3];
    const float* bq      = (const float*)d_in[4];
    const float* Wk      = (const float*)d_in[5];
    const float* bk      = (const float*)d_in[6];
    const float* Wv      = (const float*)d_in[7];
    const float* bv      = (const float*)d_in[8];
    const float* Wo      = (const float*)d_in[9];
    const float* bo      = (const float*)d_in[10];
    const float* gamma   = (const float*)d_in[11];
    const float* beta    = (const float*)d_in[12];

    float* out  = (float*)d_out;                  // [4,2048,128]
    float* attn = out + (size_t)BB * TT * DD;     // [4,8,2048,2048]

    float *Qd, *Kd, *Vd, *Cd;
    cudaGetSymbolAddress((void**)&Qd, g_Q);
    cudaGetSymbolAddress((void**)&Kd, g_K);
    cudaGetSymbolAddress((void**)&Vd, g_V);
    cudaGetSymbolAddress((void**)&Cd, g_ctx);

    const int rows = BB * TT;                     // 8192
    proj3_kernel<<<dim3(rows / 16, 3), 128>>>(queries, keys, values,
                                              Wq, bq, Wk, bk, Wv, bv,
                                              Qd, Kd, Vd);

    attn_mma_kernel<<<dim3(TT / 128, BB * HH), 128>>>(Qd, Kd, Vd, attn, Cd);

    out_kernel<<<rows / 16, 128>>>(Cd, Wo, bo, queries, gamma, beta, out);
}

// round 5
// speedup vs baseline: 3.9293x; 1.5168x over previous
#include <cuda_runtime.h>
#include <cuda_bf16.h>
#include <stdint.h>
#include <math.h>

#define BB 4
#define TT 2048
#define DD 128
#define HH 8
#define DK 16
#define KSTR 20          // K tile smem stride (floats) - conflict-free for b-frag LDS
#define VSTR 136         // V^T tile stride (bf16)

__device__ float g_Q[BB*TT*DD];
__device__ float g_K[BB*TT*DD];
__device__ float g_V[BB*TT*DD];
__device__ float g_ctx[BB*TT*DD];

// ---------------------------------------------------------------------------
__device__ __forceinline__ uint32_t f2tf32(float x) {
    uint32_t r;
    asm("cvt.rna.tf32.f32 %0, %1;" : "=r"(r) : "f"(x));
    return r;
}

__device__ __forceinline__ void mma_tf32(float c[4], const uint32_t a[4],
                                         uint32_t b0, uint32_t b1) {
    asm volatile(
        "mma.sync.aligned.m16n8k8.row.col.f32.tf32.tf32.f32 "
        "{%0,%1,%2,%3}, {%4,%5,%6,%7}, {%8,%9}, {%0,%1,%2,%3};"
        : "+f"(c[0]), "+f"(c[1]), "+f"(c[2]), "+f"(c[3])
        : "r"(a[0]), "r"(a[1]), "r"(a[2]), "r"(a[3]), "r"(b0), "r"(b1));
}

__device__ __forceinline__ void mma_bf16(float c[4], const uint32_t a[4],
                                         uint32_t b0, uint32_t b1) {
    asm volatile(
        "mma.sync.aligned.m16n8k16.row.col.f32.bf16.bf16.f32 "
        "{%0,%1,%2,%3}, {%4,%5,%6,%7}, {%8,%9}, {%0,%1,%2,%3};"
        : "+f"(c[0]), "+f"(c[1]), "+f"(c[2]), "+f"(c[3])
        : "r"(a[0]), "r"(a[1]), "r"(a[2]), "r"(a[3]), "r"(b0), "r"(b1));
}

__device__ __forceinline__ uint32_t pack_bf16x2(float lo, float hi) {
    __nv_bfloat162 v = __floats2bfloat162_rn(lo, hi);   // .x = lo half
    return *reinterpret_cast<uint32_t*>(&v);
}

// ---------------------------------------------------------------------------
// Attention kernel: grid (TT/128, BB*HH), 128 threads (4 warps, m32 per warp)
// ---------------------------------------------------------------------------
__global__ void __launch_bounds__(128, 4)
attn_mma_kernel(const float* __restrict__ Qg,
                const float* __restrict__ Kg,
                const float* __restrict__ Vg,
                float* __restrict__ attn,
                float* __restrict__ ctx)
{
    __shared__ uint32_t sKhi[128 * KSTR];
    __shared__ uint32_t sKlo[128 * KSTR];
    __shared__ uint32_t sVt[DK * (VSTR / 2)];      // bf16 V^T tile, u32 view
    __shared__ float    sRinv[128];

    const int tid  = threadIdx.x;
    const int lane = tid & 31;
    const int wq   = tid >> 5;
    const int g    = lane >> 2;      // groupID
    const int tig  = lane & 3;       // thread in group

    const int q0 = blockIdx.x * 128;
    const int bh = blockIdx.y;
    const int bb = bh >> 3;
    const int h  = bh & 7;

    // ---- Q fragments (scaled by 0.25 = 1/sqrt(dk), exact power of 2) ----
    uint32_t qhi[2][2][4], qlo[2][2][4];
    #pragma unroll
    for (int m = 0; m < 2; m++) {
        const int rm = q0 + wq * 32 + m * 16 + g;
        #pragma unroll
        for (int s = 0; s < 2; s++) {
            const int c = h * DK + s * 8 + tig;
            float x[4];
            x[0] = 0.25f * Qg[((size_t)bb * TT + rm    ) * DD + c];
            x[1] = 0.25f * Qg[((size_t)bb * TT + rm + 8) * DD + c];
            x[2] = 0.25f * Qg[((size_t)bb * TT + rm    ) * DD + c + 4];
            x[3] = 0.25f * Qg[((size_t)bb * TT + rm + 8) * DD + c + 4];
            #pragma unroll
            for (int i = 0; i < 4; i++) {
                qhi[m][s][i] = f2tf32(x[i]);
                qlo[m][s][i] = f2tf32(x[i] - __uint_as_float(qhi[m][s][i]));
            }
        }
    }

    // =============================== SWEEP 1 ===============================
    float ps[2][2] = {{0.f, 0.f}, {0.f, 0.f}};

    for (int kt = 0; kt < TT / 128; kt++) {
        __syncthreads();
        {   // load K tile (hi only)
            const int r = tid;
            const float4* Ks = (const float4*)(Kg + ((size_t)bb * TT + kt * 128 + r) * DD + h * DK);
            #pragma unroll
            for (int c4 = 0; c4 < 4; c4++) {
                float4 v = Ks[c4];
                uint4 hi;
                hi.x = f2tf32(v.x); hi.y = f2tf32(v.y);
                hi.z = f2tf32(v.z); hi.w = f2tf32(v.w);
                *(uint4*)&sKhi[r * KSTR + c4 * 4] = hi;
            }
        }
        __syncthreads();

        #pragma unroll 4
        for (int ns = 0; ns < 16; ns++) {
            uint32_t b0[2], b1[2];
            #pragma unroll
            for (int s = 0; s < 2; s++) {
                const int base = (ns * 8 + g) * KSTR + s * 8 + tig;
                b0[s] = sKhi[base];
                b1[s] = sKhi[base + 4];
            }
            #pragma unroll
            for (int m = 0; m < 2; m++) {
                float C[4] = {0.f, 0.f, 0.f, 0.f};
                mma_tf32(C, qhi[m][0], b0[0], b1[0]);
                mma_tf32(C, qhi[m][1], b0[1], b1[1]);
                ps[m][0] += __expf(C[0]) + __expf(C[1]);
                ps[m][1] += __expf(C[2]) + __expf(C[3]);
            }
        }
    }

    // quad reduce + publish 1/rowsum
    #pragma unroll
    for (int m = 0; m < 2; m++) {
        #pragma unroll
        for (int i = 0; i < 2; i++) {
            float v = ps[m][i];
            v += __shfl_xor_sync(0xffffffffu, v, 1);
            v += __shfl_xor_sync(0xffffffffu, v, 2);
            ps[m][i] = v;
        }
        if (tig == 0) {
            sRinv[wq * 32 + m * 16 + g]     = 1.0f / ps[m][0];
            sRinv[wq * 32 + m * 16 + g + 8] = 1.0f / ps[m][1];
        }
    }
    __syncthreads();
    float ri[2][2];
    #pragma unroll
    for (int m = 0; m < 2; m++) {
        ri[m][0] = sRinv[wq * 32 + m * 16 + g];
        ri[m][1] = sRinv[wq * 32 + m * 16 + g + 8];
    }

    // =============================== SWEEP 2 ===============================
    float cc[2][2][4];
    #pragma unroll
    for (int m = 0; m < 2; m++)
        #pragma unroll
        for (int n = 0; n < 2; n++)
            #pragma unroll
            for (int i = 0; i < 4; i++) cc[m][n][i] = 0.f;

    const size_t abase_w = ((size_t)bh * TT + q0 + wq * 32) * TT;

    for (int kt = 0; kt < TT / 128; kt++) {
        __syncthreads();
        {   // load K (hi+lo) and V^T (bf16)
            const int r = tid;
            const float4* Ks = (const float4*)(Kg + ((size_t)bb * TT + kt * 128 + r) * DD + h * DK);
            const float4* Vs = (const float4*)(Vg + ((size_t)bb * TT + kt * 128 + r) * DD + h * DK);
            __nv_bfloat16* vt = (__nv_bfloat16*)sVt;
            #pragma unroll
            for (int c4 = 0; c4 < 4; c4++) {
                float4 v = Ks[c4];
                uint4 hi, lo;
                hi.x = f2tf32(v.x); lo.x = f2tf32(v.x - __uint_as_float(hi.x));
                hi.y = f2tf32(v.y); lo.y = f2tf32(v.y - __uint_as_float(hi.y));
                hi.z = f2tf32(v.z); lo.z = f2tf32(v.z - __uint_as_float(hi.z));
                hi.w = f2tf32(v.w); lo.w = f2tf32(v.w - __uint_as_float(hi.w));
                *(uint4*)&sKhi[r * KSTR + c4 * 4] = hi;
                *(uint4*)&sKlo[r * KSTR + c4 * 4] = lo;

                float4 vv = Vs[c4];
                vt[(c4 * 4 + 0) * VSTR + r] = __float2bfloat16(vv.x);
                vt[(c4 * 4 + 1) * VSTR + r] = __float2bfloat16(vv.y);
                vt[(c4 * 4 + 2) * VSTR + r] = __float2bfloat16(vv.z);
                vt[(c4 * 4 + 3) * VSTR + r] = __float2bfloat16(vv.w);
            }
        }
        __syncthreads();

        #pragma unroll 2
        for (int j = 0; j < 8; j++) {          // ns pairs -> one k16 for ctx mma
            uint32_t apk[2][4];
            #pragma unroll
            for (int nsl = 0; nsl < 2; nsl++) {
                const int ns = 2 * j + nsl;
                uint32_t bh0[2], bh1[2], bl0[2], bl1[2];
                #pragma unroll
                for (int s = 0; s < 2; s++) {
                    const int base = (ns * 8 + g) * KSTR + s * 8 + tig;
                    bh0[s] = sKhi[base];  bh1[s] = sKhi[base + 4];
                    bl0[s] = sKlo[base];  bl1[s] = sKlo[base + 4];
                }
                #pragma unroll
                for (int m = 0; m < 2; m++) {
                    float C[4] = {0.f, 0.f, 0.f, 0.f};
                    #pragma unroll
                    for (int s = 0; s < 2; s++) {
                        mma_tf32(C, qhi[m][s], bh0[s], bh1[s]);
                        mma_tf32(C, qhi[m][s], bl0[s], bl1[s]);
                        mma_tf32(C, qlo[m][s], bh0[s], bh1[s]);
                    }
                    const float p0 = __expf(C[0]) * ri[m][0];
                    const float p1 = __expf(C[1]) * ri[m][0];
                    const float p2 = __expf(C[2]) * ri[m][1];
                    const float p3 = __expf(C[3]) * ri[m][1];

                    // attn store (normalized, fp32, 32B sectors per quad)
                    float* ap = attn + abase_w + (size_t)(m * 16 + g) * TT
                              + kt * 128 + ns * 8 + 2 * tig;
                    *(float2*)ap            = make_float2(p0, p1);
                    *(float2*)(ap + 8 * TT) = make_float2(p2, p3);

                    // pack for ctx A fragment (C layout == bf16 A layout)
                    apk[m][nsl ? 2 : 0] = pack_bf16x2(p0, p1);
                    apk[m][nsl ? 3 : 1] = pack_bf16x2(p2, p3);
                }
            }
            // ctx += P(16 cols) @ V
            #pragma unroll
            for (int n2 = 0; n2 < 2; n2++) {
                const int vi = (n2 * 8 + g) * (VSTR / 2) + 8 * j + tig;
                const uint32_t vb0 = sVt[vi];
                const uint32_t vb1 = sVt[vi + 4];
                mma_bf16(cc[0][n2], apk[0], vb0, vb1);
                mma_bf16(cc[1][n2], apk[1], vb0, vb1);
            }
        }
    }

    // ---- write ctx ----
    #pragma unroll
    for (int m = 0; m < 2; m++) {
        const int row = q0 + wq * 32 + m * 16 + g;
        #pragma unroll
        for (int n2 = 0; n2 < 2; n2++) {
            float* cp = ctx + ((size_t)bb * TT + row) * DD + h * DK + n2 * 8 + 2 * tig;
            *(float2*)cp            = make_float2(cc[m][n2][0], cc[m][n2][1]);
            *(float2*)(cp + 8 * DD) = make_float2(cc[m][n2][2], cc[m][n2][3]);
        }
    }
}

// ---------------------------------------------------------------------------
// Merged QKV projection: grid (rows/16, 3), 128 threads
// ---------------------------------------------------------------------------
__global__ void proj3_kernel(const float* __restrict__ q,
                             const float* __restrict__ k,
                             const float* __restrict__ v,
                             const float* __restrict__ Wq, const float* __restrict__ bq,
                             const float* __restrict__ Wk, const float* __restrict__ bk,
                             const float* __restrict__ Wv, const float* __restrict__ bv,
                             float* __restrict__ Qd, float* __restrict__ Kd,
                             float* __restrict__ Vd)
{
    const float* X; const float* W; const float* bias; float* out;
    if (blockIdx.y == 0)      { X = q; W = Wq; bias = bq; out = Qd; }
    else if (blockIdx.y == 1) { X = k; W = Wk; bias = bk; out = Kd; }
    else                      { X = v; W = Wv; bias = bv; out = Vd; }

    __shared__ float xs[16][128];
    const int tid  = threadIdx.x;
    const int row0 = blockIdx.x * 16;

    #pragma unroll
    for (int r = 0; r < 16; r++)
        xs[r][tid] = X[(size_t)(row0 + r) * DD + tid];
    __syncthreads();

    float acc[16];
    const float bvv = bias[tid];
    #pragma unroll
    for (int r = 0; r < 16; r++) acc[r] = bvv;

    for (int kk = 0; kk < DD; kk++) {
        const float wv = W[kk * DD + tid];
        #pragma unroll
        for (int r = 0; r < 16; r++)
            acc[r] = fmaf(xs[r][kk], wv, acc[r]);
    }

    #pragma unroll
    for (int r = 0; r < 16; r++)
        out[(size_t)(row0 + r) * DD + tid] = acc[r];
}

// ---------------------------------------------------------------------------
// Output projection + residual + LayerNorm
// ---------------------------------------------------------------------------
__global__ void out_kernel(const float* __restrict__ ctxg,
                           const float* __restrict__ Wo,
                           const float* __restrict__ bo,
                           const float* __restrict__ resid,
                           const float* __restrict__ gamma,
                           const float* __restrict__ beta,
                           float* __restrict__ out)
{
    __shared__ float xs[16][128];
    __shared__ float mrow[16], rrow[16];
    const int tid  = threadIdx.x;   // 128
    const int row0 = blockIdx.x * 16;

    #pragma unroll
    for (int r = 0; r < 16; r++)
        xs[r][tid] = ctxg[(size_t)(row0 + r) * DD + tid];
    __syncthreads();

    float acc[16];
    const float bv = bo[tid];
    #pragma unroll
    for (int r = 0; r < 16; r++) acc[r] = bv;
    for (int k = 0; k < DD; k++) {
        const float wv = Wo[k * DD + tid];
        #pragma unroll
        for (int r = 0; r < 16; r++)
            acc[r] = fmaf(xs[r][k], wv, acc[r]);
    }
    __syncthreads();

    #pragma unroll
    for (int r = 0; r < 16; r++) {
        acc[r] += resid[(size_t)(row0 + r) * DD + tid];
        xs[r][tid] = acc[r];
    }
    __syncthreads();

    {
        const int r = tid >> 3, l8 = tid & 7;
        float s = 0.f, s2 = 0.f;
        for (int c = l8; c < 128; c += 8) {
            const float v = xs[r][c];
            s += v; s2 = fmaf(v, v, s2);
        }
        #pragma unroll
        for (int off = 4; off > 0; off >>= 1) {
            s  += __shfl_down_sync(0xffffffffu, s,  off, 8);
            s2 += __shfl_down_sync(0xffffffffu, s2, off, 8);
        }
        if (l8 == 0) {
            const float m   = s * (1.f / 128.f);
            const float var = s2 * (1.f / 128.f) - m * m;
            mrow[r] = m;
            rrow[r] = rsqrtf(var + 1e-5f);
        }
    }
    __syncthreads();

    const float gm = gamma[tid], bt = beta[tid];
    #pragma unroll
    for (int r = 0; r < 16; r++)
        out[(size_t)(row0 + r) * DD + tid] = (acc[r] - mrow[r]) * rrow[r] * gm + bt;
}

// ---------------------------------------------------------------------------
extern "C" void kernel_launch(void* const* d_in, const int* in_sizes, int n_in,
                              void* d_out, int out_size)
{
    const float* queries = (const float*)d_in[0];
    const float* keys    = (const float*)d_in[1];
    const float* values  = (const float*)d_in[2];
    const float* Wq      = (const float*)d_in[3];
    const float* bq      = (const float*)d_in[4];
    const float* Wk      = (const float*)d_in[5];
    const float* bk      = (const float*)d_in[6];
    const float* Wv      = (const float*)d_in[7];
    const float* bv      = (const float*)d_in[8];
    const float* Wo      = (const float*)d_in[9];
    const float* bo      = (const float*)d_in[10];
    const float* gamma   = (const float*)d_in[11];
    const float* beta    = (const float*)d_in[12];

    float* out  = (float*)d_out;                  // [4,2048,128]
    float* attn = out + (size_t)BB * TT * DD;     // [4,8,2048,2048]

    float *Qd, *Kd, *Vd, *Cd;
    cudaGetSymbolAddress((void**)&Qd, g_Q);
    cudaGetSymbolAddress((void**)&Kd, g_K);
    cudaGetSymbolAddress((void**)&Vd, g_V);
    cudaGetSymbolAddress((void**)&Cd, g_ctx);

    const int rows = BB * TT;                     // 8192
    proj3_kernel<<<dim3(rows / 16, 3), 128>>>(queries, keys, values,
                                              Wq, bq, Wk, bk, Wv, bv,
                                              Qd, Kd, Vd);

    attn_mma_kernel<<<dim3(TT / 128, BB * HH), 128>>>(Qd, Kd, Vd, attn, Cd);

    out_kernel<<<rows / 16, 128>>>(Cd, Wo, bo, queries, gamma, beta, out);
}